// round 3
// baseline (speedup 1.0000x reference)
#include <cuda_runtime.h>
#include <math.h>

#define NB 16      // batches
#define NS 4096    // segments per batch
#define ND 256     // embedding dim
#define NCHUNK 32  // chunks per batch (stage-1 grid.x)
#define ROWS_PER_CTA (NS / NCHUNK)          // 128
#define CTA_THREADS 256
#define NWARP (CTA_THREADS / 32)            // 8
#define ROWS_PER_WARP (ROWS_PER_CTA / NWARP) // 16

// Scratch: partial sums of normalized rows.
// Layout: [tensor(2)][batch(16)][chunk(32)][dim(256)]  = 1 MiB
__device__ float g_partial[2 * NB * NCHUNK * ND];

// Process ROWS_PER_WARP rows of one tensor for (batch, chunk, warp),
// accumulating the normalized-row sum into smem acc[256] via shared atomics.
__device__ __forceinline__ void process_tensor(const float* __restrict__ x,
                                               float* __restrict__ acc,
                                               int batch, int chunk,
                                               int warp, int lane) {
    float a0 = 0.f, a1 = 0.f, a2 = 0.f, a3 = 0.f;
    float a4 = 0.f, a5 = 0.f, a6 = 0.f, a7 = 0.f;

    const int row0 = chunk * ROWS_PER_CTA + warp * ROWS_PER_WARP;
    const float* base = x + ((size_t)batch * NS + row0) * ND;

#pragma unroll 4
    for (int r = 0; r < ROWS_PER_WARP; r++) {
        const float4* rowp = (const float4*)(base + (size_t)r * ND);
        // lane l covers dims [4l,4l+4) and [128+4l, 128+4l+4): fully coalesced
        float4 v0 = rowp[lane];
        float4 v1 = rowp[lane + 32];

        float ss = v0.x * v0.x + v0.y * v0.y + v0.z * v0.z + v0.w * v0.w
                 + v1.x * v1.x + v1.y * v1.y + v1.z * v1.z + v1.w * v1.w;
#pragma unroll
        for (int o = 16; o > 0; o >>= 1)
            ss += __shfl_xor_sync(0xFFFFFFFFu, ss, o);

        float inv = 1.0f / fmaxf(sqrtf(ss), 1e-8f);

        a0 += v0.x * inv; a1 += v0.y * inv; a2 += v0.z * inv; a3 += v0.w * inv;
        a4 += v1.x * inv; a5 += v1.y * inv; a6 += v1.z * inv; a7 += v1.w * inv;
    }

    const int d0 = 4 * lane;
    atomicAdd(&acc[d0 + 0], a0);
    atomicAdd(&acc[d0 + 1], a1);
    atomicAdd(&acc[d0 + 2], a2);
    atomicAdd(&acc[d0 + 3], a3);
    atomicAdd(&acc[128 + d0 + 0], a4);
    atomicAdd(&acc[128 + d0 + 1], a5);
    atomicAdd(&acc[128 + d0 + 2], a6);
    atomicAdd(&acc[128 + d0 + 3], a7);
}

__global__ __launch_bounds__(CTA_THREADS)
void ed_stage1(const float* __restrict__ x1, const float* __restrict__ x2) {
    __shared__ float acc1[ND];
    __shared__ float acc2[ND];

    const int tid   = threadIdx.x;
    const int warp  = tid >> 5;
    const int lane  = tid & 31;
    const int chunk = blockIdx.x;
    const int batch = blockIdx.y;

    acc1[tid] = 0.0f;
    acc2[tid] = 0.0f;
    __syncthreads();

    process_tensor(x1, acc1, batch, chunk, warp, lane);
    process_tensor(x2, acc2, batch, chunk, warp, lane);

    __syncthreads();

    // one write per thread per tensor (each (t,b,c,d) written exactly once per launch)
    g_partial[((size_t)(0 * NB + batch) * NCHUNK + chunk) * ND + tid] = acc1[tid];
    g_partial[((size_t)(1 * NB + batch) * NCHUNK + chunk) * ND + tid] = acc2[tid];
}

__global__ __launch_bounds__(ND)
void ed_stage2(float* __restrict__ out) {
    const int b = blockIdx.x;
    const int d = threadIdx.x;

    float s1 = 0.f, s2 = 0.f;
#pragma unroll
    for (int c = 0; c < NCHUNK; c++) {
        s1 += g_partial[((size_t)(0 * NB + b) * NCHUNK + c) * ND + d];
        s2 += g_partial[((size_t)(1 * NB + b) * NCHUNK + c) * ND + d];
    }

    __shared__ float red[ND];
    red[d] = s1 * s2;
    __syncthreads();
#pragma unroll
    for (int s = ND / 2; s > 0; s >>= 1) {
        if (d < s) red[d] += red[d + s];
        __syncthreads();
    }

    if (d == 0) {
        // dot(mean1, mean2) = (sum1 . sum2) / (S*S)
        out[b] = 1.0f - red[0] / ((float)NS * (float)NS);
    }
}

extern "C" void kernel_launch(void* const* d_in, const int* in_sizes, int n_in,
                              void* d_out, int out_size) {
    const float* x1 = (const float*)d_in[0];
    const float* x2 = (const float*)d_in[1];
    float* out = (float*)d_out;

    dim3 grid1(NCHUNK, NB);
    ed_stage1<<<grid1, CTA_THREADS>>>(x1, x2);
    ed_stage2<<<NB, ND>>>(out);
}

// round 7
// speedup vs baseline: 1.2554x; 1.2554x over previous
#include <cuda_runtime.h>
#include <math.h>

#define NB 16      // batches
#define NS 4096    // segments per batch
#define ND 256     // embedding dim
#define NCHUNK 32  // chunks per batch (grid.x)
#define ROWS_PER_CTA (NS / NCHUNK)           // 128
#define CTA_THREADS 256
#define NWARP (CTA_THREADS / 32)             // 8
#define ROWS_PER_WARP (ROWS_PER_CTA / NWARP) // 16

// Scratch: partial sums of normalized rows.
// Layout: [tensor(2)][batch(16)][chunk(32)][dim(256)] = 1 MiB
__device__ float g_partial[2 * NB * NCHUNK * ND];
// Per-batch completion counters (reset to 0 by the finishing CTA -> replay-safe)
__device__ unsigned int g_count[NB];

// Process ROWS_PER_WARP rows of one tensor, 2 rows per iteration so that
// two independent load+shuffle chains are in flight.
__device__ __forceinline__ void process_tensor(const float* __restrict__ x,
                                               float* __restrict__ acc,
                                               int batch, int chunk,
                                               int warp, int lane) {
    float a0 = 0.f, a1 = 0.f, a2 = 0.f, a3 = 0.f;
    float a4 = 0.f, a5 = 0.f, a6 = 0.f, a7 = 0.f;

    const int row0 = chunk * ROWS_PER_CTA + warp * ROWS_PER_WARP;
    const float* base = x + ((size_t)batch * NS + row0) * ND;

#pragma unroll
    for (int r = 0; r < ROWS_PER_WARP; r += 2) {
        const float4* rpA = (const float4*)(base + (size_t)r * ND);
        const float4* rpB = (const float4*)(base + (size_t)(r + 1) * ND);
        // lane l covers dims [4l,4l+4) and [128+4l,128+4l+4): fully coalesced
        float4 a0v = rpA[lane];
        float4 a1v = rpA[lane + 32];
        float4 b0v = rpB[lane];
        float4 b1v = rpB[lane + 32];

        float ssA = a0v.x * a0v.x + a0v.y * a0v.y + a0v.z * a0v.z + a0v.w * a0v.w
                  + a1v.x * a1v.x + a1v.y * a1v.y + a1v.z * a1v.z + a1v.w * a1v.w;
        float ssB = b0v.x * b0v.x + b0v.y * b0v.y + b0v.z * b0v.z + b0v.w * b0v.w
                  + b1v.x * b1v.x + b1v.y * b1v.y + b1v.z * b1v.z + b1v.w * b1v.w;

        // interleaved independent butterfly chains
#pragma unroll
        for (int o = 16; o > 0; o >>= 1) {
            ssA += __shfl_xor_sync(0xFFFFFFFFu, ssA, o);
            ssB += __shfl_xor_sync(0xFFFFFFFFu, ssB, o);
        }

        // x / max(||x||, 1e-8)  ==  x * rsqrt(max(ss, 1e-16)) for ||x|| > eps
        float invA = rsqrtf(fmaxf(ssA, 1e-16f));
        float invB = rsqrtf(fmaxf(ssB, 1e-16f));

        a0 += a0v.x * invA + b0v.x * invB;
        a1 += a0v.y * invA + b0v.y * invB;
        a2 += a0v.z * invA + b0v.z * invB;
        a3 += a0v.w * invA + b0v.w * invB;
        a4 += a1v.x * invA + b1v.x * invB;
        a5 += a1v.y * invA + b1v.y * invB;
        a6 += a1v.z * invA + b1v.z * invB;
        a7 += a1v.w * invA + b1v.w * invB;
    }

    const int d0 = 4 * lane;
    atomicAdd(&acc[d0 + 0], a0);
    atomicAdd(&acc[d0 + 1], a1);
    atomicAdd(&acc[d0 + 2], a2);
    atomicAdd(&acc[d0 + 3], a3);
    atomicAdd(&acc[128 + d0 + 0], a4);
    atomicAdd(&acc[128 + d0 + 1], a5);
    atomicAdd(&acc[128 + d0 + 2], a6);
    atomicAdd(&acc[128 + d0 + 3], a7);
}

__global__ __launch_bounds__(CTA_THREADS)
void ed_fused(const float* __restrict__ x1, const float* __restrict__ x2,
              float* __restrict__ out) {
    __shared__ float acc1[ND];
    __shared__ float acc2[ND];
    __shared__ unsigned int s_is_last;

    const int tid   = threadIdx.x;
    const int warp  = tid >> 5;
    const int lane  = tid & 31;
    const int chunk = blockIdx.x;
    const int batch = blockIdx.y;

    acc1[tid] = 0.0f;
    acc2[tid] = 0.0f;
    __syncthreads();

    process_tensor(x1, acc1, batch, chunk, warp, lane);
    process_tensor(x2, acc2, batch, chunk, warp, lane);

    __syncthreads();

    // publish this chunk's partials (each slot written exactly once per launch)
    g_partial[((size_t)(0 * NB + batch) * NCHUNK + chunk) * ND + tid] = acc1[tid];
    g_partial[((size_t)(1 * NB + batch) * NCHUNK + chunk) * ND + tid] = acc2[tid];

    __threadfence();
    if (tid == 0) {
        unsigned int old = atomicAdd(&g_count[batch], 1u);
        s_is_last = (old == NCHUNK - 1) ? 1u : 0u;
    }
    __syncthreads();

    if (s_is_last) {
        __threadfence();  // ensure all published partials are visible

        // reduce 32 chunks for this batch; data is L2-hot
        float s1 = 0.f, s2 = 0.f;
#pragma unroll
        for (int c = 0; c < NCHUNK; c++) {
            s1 += g_partial[((size_t)(0 * NB + batch) * NCHUNK + c) * ND + tid];
            s2 += g_partial[((size_t)(1 * NB + batch) * NCHUNK + c) * ND + tid];
        }

        // block-reduce dot = sum_d s1[d]*s2[d]; reuse acc1 as scratch
        float p = s1 * s2;
#pragma unroll
        for (int o = 16; o > 0; o >>= 1)
            p += __shfl_xor_sync(0xFFFFFFFFu, p, o);
        if (lane == 0) acc1[warp] = p;
        __syncthreads();
        if (warp == 0) {
            float q = (lane < NWARP) ? acc1[lane] : 0.f;
#pragma unroll
            for (int o = 4; o > 0; o >>= 1)
                q += __shfl_xor_sync(0xFFFFFFFFu, q, o);
            if (lane == 0) {
                // dot(mean1, mean2) = (sum1 . sum2) / (S*S)
                out[batch] = 1.0f - q / ((float)NS * (float)NS);
                g_count[batch] = 0u;  // reset for next graph replay
            }
        }
    }
}

extern "C" void kernel_launch(void* const* d_in, const int* in_sizes, int n_in,
                              void* d_out, int out_size) {
    const float* x1 = (const float*)d_in[0];
    const float* x2 = (const float*)d_in[1];
    float* out = (float*)d_out;

    dim3 grid(NCHUNK, NB);
    ed_fused<<<grid, CTA_THREADS>>>(x1, x2, out);
}